// round 1
// baseline (speedup 1.0000x reference)
#include <cuda_runtime.h>
#include <math.h>

// Problem constants
#define Bn  2
#define Sn  2048
#define Dn  2048
#define Hn  16
#define DHn 128
#define Mn  (Bn*Sn)          // 4096 rows for all GEMMs

// ---------------------------------------------------------------------------
// Scratch (no allocation allowed -> __device__ globals)
// ---------------------------------------------------------------------------
__device__ float g_Q[(size_t)Bn*Sn*Dn];
__device__ float g_K[(size_t)Bn*Sn*Dn];
__device__ float g_V[(size_t)Bn*Sn*Dn];
__device__ float g_O[(size_t)Bn*Sn*Dn];
__device__ float g_ct[Sn*64];
__device__ float g_st[Sn*64];

// ---------------------------------------------------------------------------
// GEMM: C[m,n] = sum_k A[m,k]*W[n,k] + bias[n]
// A: Md x Kd row-major, W: Nd x Kd row-major (both K-contiguous -> NT gemm)
// 128x128 block tile, BK=8, 8x8 per thread, 256 threads.
// ---------------------------------------------------------------------------
__global__ __launch_bounds__(256) void sgemm_nt_bias(
    const float* __restrict__ A, const float* __restrict__ W,
    const float* __restrict__ bias, float* __restrict__ C,
    int Md, int Nd, int Kd)
{
    __shared__ float As[8][132];   // k-major, +4 pad
    __shared__ float Ws[8][132];

    const int tid = threadIdx.x;
    const int tx  = tid & 15;
    const int ty  = tid >> 4;
    const int bm  = blockIdx.y * 128;
    const int bn  = blockIdx.x * 128;

    const int lrow = tid >> 1;        // 0..127
    const int lk   = (tid & 1) * 4;   // 0 or 4

    float acc[8][8];
#pragma unroll
    for (int i = 0; i < 8; i++)
#pragma unroll
        for (int j = 0; j < 8; j++) acc[i][j] = 0.f;

    const float* Ap = A + (size_t)(bm + lrow) * Kd + lk;
    const float* Wp = W + (size_t)(bn + lrow) * Kd + lk;

    float4 ra = *(const float4*)Ap;
    float4 rw = *(const float4*)Wp;

    for (int k0 = 0; k0 < Kd; k0 += 8) {
        As[lk + 0][lrow] = ra.x; As[lk + 1][lrow] = ra.y;
        As[lk + 2][lrow] = ra.z; As[lk + 3][lrow] = ra.w;
        Ws[lk + 0][lrow] = rw.x; Ws[lk + 1][lrow] = rw.y;
        Ws[lk + 2][lrow] = rw.z; Ws[lk + 3][lrow] = rw.w;
        __syncthreads();

        if (k0 + 8 < Kd) {                       // prefetch next slab
            ra = *(const float4*)(Ap + k0 + 8);
            rw = *(const float4*)(Wp + k0 + 8);
        }

#pragma unroll
        for (int kk = 0; kk < 8; kk++) {
            float a[8], b[8];
            *(float4*)&a[0] = *(const float4*)&As[kk][ty * 8];
            *(float4*)&a[4] = *(const float4*)&As[kk][ty * 8 + 4];
            *(float4*)&b[0] = *(const float4*)&Ws[kk][tx * 8];
            *(float4*)&b[4] = *(const float4*)&Ws[kk][tx * 8 + 4];
#pragma unroll
            for (int i = 0; i < 8; i++)
#pragma unroll
                for (int j = 0; j < 8; j++)
                    acc[i][j] = fmaf(a[i], b[j], acc[i][j]);
        }
        __syncthreads();
    }

    float bv[8];
#pragma unroll
    for (int j = 0; j < 8; j++) bv[j] = bias[bn + tx * 8 + j];

#pragma unroll
    for (int i = 0; i < 8; i++) {
        float* cp = C + (size_t)(bm + ty * 8 + i) * Nd + bn + tx * 8;
        float4 o0 = make_float4(acc[i][0] + bv[0], acc[i][1] + bv[1],
                                acc[i][2] + bv[2], acc[i][3] + bv[3]);
        float4 o1 = make_float4(acc[i][4] + bv[4], acc[i][5] + bv[5],
                                acc[i][6] + bv[6], acc[i][7] + bv[7]);
        *(float4*)cp       = o0;
        *(float4*)(cp + 4) = o1;
    }
}

// ---------------------------------------------------------------------------
// RoPE cos/sin table in fp64 (exact angles; recomputed every launch)
// ---------------------------------------------------------------------------
__global__ void rope_table_kernel()
{
    int idx = blockIdx.x * blockDim.x + threadIdx.x;
    if (idx >= Sn * 64) return;
    int i = idx & 63;
    int s = idx >> 6;
    double inv = exp((double)(-2 * i) * (9.210340371976182736 / 128.0)); // ln(1e4)
    double ang = (double)s * inv;
    g_ct[idx] = (float)cos(ang);
    g_st[idx] = (float)sin(ang);
}

// ---------------------------------------------------------------------------
// RoPE apply (in-place), pair (i, i+64) within each head
// ---------------------------------------------------------------------------
__global__ void rope_apply_kernel(float* __restrict__ X)
{
    int idx = blockIdx.x * blockDim.x + threadIdx.x;
    if (idx >= Bn * Sn * Hn * 64) return;
    int i = idx & 63;
    int h = (idx >> 6) & (Hn - 1);
    int s = (idx >> 10) & (Sn - 1);
    int b = idx >> 21;
    size_t base = (size_t)(b * Sn + s) * Dn + h * DHn;
    float c  = g_ct[(s << 6) | i];
    float sv = g_st[(s << 6) | i];
    float x1 = X[base + i];
    float x2 = X[base + 64 + i];
    X[base + i]      = x1 * c - x2 * sv;
    X[base + 64 + i] = x2 * c + x1 * sv;
}

// ---------------------------------------------------------------------------
// Flash attention, fp32. One block = 64 q-rows of one (b,h).
// smem: sQ[d][r] 128x68, sKV (K[d][c] 128x68 | V[c][d] 64x128), sP[c][r] 64x68
// 256 threads: 16x16; score tile 4x4 per thread; output tile 4x8 per thread.
// 1/sqrt(Dh) folded into Q load.
// ---------------------------------------------------------------------------
#define FA_SMEM_FLOATS (128*68 + 128*68 + 64*68)
#define FA_SMEM_BYTES  (FA_SMEM_FLOATS * 4)

__global__ __launch_bounds__(256) void flash_attn_kernel(
    const float* __restrict__ Q, const float* __restrict__ K,
    const float* __restrict__ V, float* __restrict__ O)
{
    extern __shared__ float sm[];
    float* sQ  = sm;                 // [128][68] transposed
    float* sKV = sm + 128 * 68;      // K transposed [128][68], later V [64][128]
    float* sP  = sm + 2 * 128 * 68;  // [64][68]  (c-major)

    const int tid = threadIdx.x;
    const int tx  = tid & 15;
    const int ty  = tid >> 4;
    const int qt  = blockIdx.x;      // q tile 0..31
    const int bh  = blockIdx.y;      // 0..31
    const int b   = bh >> 4;
    const int h   = bh & 15;

    const float scale = 0.088388347648318447f;   // 1/sqrt(128)

    // ---- load Q tile transposed (scaled) ----
    {
        const int d4 = tid & 31;
        const int r0 = tid >> 5;
#pragma unroll
        for (int i = 0; i < 8; i++) {
            int r = r0 + i * 8;
            float4 v4 = *(const float4*)(Q + ((size_t)(b * Sn + qt * 64 + r) * Dn
                                              + h * DHn + d4 * 4));
            sQ[(d4 * 4 + 0) * 68 + r] = v4.x * scale;
            sQ[(d4 * 4 + 1) * 68 + r] = v4.y * scale;
            sQ[(d4 * 4 + 2) * 68 + r] = v4.z * scale;
            sQ[(d4 * 4 + 3) * 68 + r] = v4.w * scale;
        }
    }

    float m_i[4], l_i[4], acc[4][8];
#pragma unroll
    for (int i = 0; i < 4; i++) {
        m_i[i] = -1e30f;
        l_i[i] = 0.f;
#pragma unroll
        for (int j = 0; j < 8; j++) acc[i][j] = 0.f;
    }

    for (int jt = 0; jt < Sn / 64; jt++) {
        // ---- load K tile transposed ----
        {
            const int d4 = tid & 31;
            const int c0 = tid >> 5;
#pragma unroll
            for (int i = 0; i < 8; i++) {
                int c = c0 + i * 8;
                float4 v4 = *(const float4*)(K + ((size_t)(b * Sn + jt * 64 + c) * Dn
                                                  + h * DHn + d4 * 4));
                sKV[(d4 * 4 + 0) * 68 + c] = v4.x;
                sKV[(d4 * 4 + 1) * 68 + c] = v4.y;
                sKV[(d4 * 4 + 2) * 68 + c] = v4.z;
                sKV[(d4 * 4 + 3) * 68 + c] = v4.w;
            }
        }
        __syncthreads();

        // ---- S = (scaled Q) K^T, 4x4 per thread ----
        float s_acc[4][4];
#pragma unroll
        for (int i = 0; i < 4; i++)
#pragma unroll
            for (int j = 0; j < 4; j++) s_acc[i][j] = 0.f;

#pragma unroll 8
        for (int d = 0; d < 128; d++) {
            float4 qa = *(const float4*)&sQ[d * 68 + ty * 4];
            float4 kb = *(const float4*)&sKV[d * 68 + tx * 4];
            float qr[4] = {qa.x, qa.y, qa.z, qa.w};
            float kr[4] = {kb.x, kb.y, kb.z, kb.w};
#pragma unroll
            for (int i = 0; i < 4; i++)
#pragma unroll
                for (int j = 0; j < 4; j++)
                    s_acc[i][j] = fmaf(qr[i], kr[j], s_acc[i][j]);
        }
        __syncthreads();   // done reading K region

        // ---- online softmax ----
        float rmax[4];
#pragma unroll
        for (int i = 0; i < 4; i++) {
            rmax[i] = s_acc[i][0];
#pragma unroll
            for (int j = 1; j < 4; j++) rmax[i] = fmaxf(rmax[i], s_acc[i][j]);
        }
#pragma unroll
        for (int off = 8; off > 0; off >>= 1)
#pragma unroll
            for (int i = 0; i < 4; i++)
                rmax[i] = fmaxf(rmax[i], __shfl_xor_sync(0xffffffffu, rmax[i], off));

        float psum[4];
#pragma unroll
        for (int i = 0; i < 4; i++) {
            float mn  = fmaxf(m_i[i], rmax[i]);
            float cor = __expf(m_i[i] - mn);
            m_i[i] = mn;
            l_i[i] *= cor;
#pragma unroll
            for (int jj = 0; jj < 8; jj++) acc[i][jj] *= cor;
            float ps = 0.f;
#pragma unroll
            for (int j = 0; j < 4; j++) {
                float p = __expf(s_acc[i][j] - mn);
                sP[(tx * 4 + j) * 68 + (ty * 4 + i)] = p;
                ps += p;
            }
            psum[i] = ps;
        }
#pragma unroll
        for (int off = 8; off > 0; off >>= 1)
#pragma unroll
            for (int i = 0; i < 4; i++)
                psum[i] += __shfl_xor_sync(0xffffffffu, psum[i], off);
#pragma unroll
        for (int i = 0; i < 4; i++) l_i[i] += psum[i];

        // ---- load V tile (row-major) into the K buffer ----
        {
            const int d4 = tid & 31;
            const int c0 = tid >> 5;
#pragma unroll
            for (int i = 0; i < 8; i++) {
                int c = c0 + i * 8;
                float4 v4 = *(const float4*)(V + ((size_t)(b * Sn + jt * 64 + c) * Dn
                                                  + h * DHn + d4 * 4));
                *(float4*)&sKV[c * 128 + d4 * 4] = v4;
            }
        }
        __syncthreads();   // P and V visible

        // ---- O += P V, 4x8 per thread ----
#pragma unroll 4
        for (int c = 0; c < 64; c++) {
            float4 pa = *(const float4*)&sP[c * 68 + ty * 4];
            float4 v0 = *(const float4*)&sKV[c * 128 + tx * 8];
            float4 v1 = *(const float4*)&sKV[c * 128 + tx * 8 + 4];
            float pr[4] = {pa.x, pa.y, pa.z, pa.w};
            float vr[8] = {v0.x, v0.y, v0.z, v0.w, v1.x, v1.y, v1.z, v1.w};
#pragma unroll
            for (int i = 0; i < 4; i++)
#pragma unroll
                for (int jj = 0; jj < 8; jj++)
                    acc[i][jj] = fmaf(pr[i], vr[jj], acc[i][jj]);
        }
        __syncthreads();   // done with V/P before next K overwrite
    }

    // ---- normalize + write O (layout [B,S,H*Dh] for the final GEMM) ----
#pragma unroll
    for (int i = 0; i < 4; i++) {
        float inv_l = 1.f / l_i[i];
        size_t row = (size_t)(b * Sn + qt * 64 + ty * 4 + i) * Dn + h * DHn + tx * 8;
        float4 o0 = make_float4(acc[i][0] * inv_l, acc[i][1] * inv_l,
                                acc[i][2] * inv_l, acc[i][3] * inv_l);
        float4 o1 = make_float4(acc[i][4] * inv_l, acc[i][5] * inv_l,
                                acc[i][6] * inv_l, acc[i][7] * inv_l);
        *(float4*)&O[row]     = o0;
        *(float4*)&O[row + 4] = o1;
    }
}

// ---------------------------------------------------------------------------
// Launch
// ---------------------------------------------------------------------------
extern "C" void kernel_launch(void* const* d_in, const int* in_sizes, int n_in,
                              void* d_out, int out_size)
{
    const float* x     = (const float*)d_in[0];
    const float* q_w   = (const float*)d_in[1];
    const float* k_w   = (const float*)d_in[2];
    const float* v_w   = (const float*)d_in[3];
    const float* q_b   = (const float*)d_in[4];
    const float* k_b   = (const float*)d_in[5];
    const float* v_b   = (const float*)d_in[6];
    const float* out_w = (const float*)d_in[7];
    const float* out_b = (const float*)d_in[8];
    float* out = (float*)d_out;

    float *pQ, *pK, *pV, *pO;
    cudaGetSymbolAddress((void**)&pQ, g_Q);
    cudaGetSymbolAddress((void**)&pK, g_K);
    cudaGetSymbolAddress((void**)&pV, g_V);
    cudaGetSymbolAddress((void**)&pO, g_O);

    cudaFuncSetAttribute(flash_attn_kernel,
                         cudaFuncAttributeMaxDynamicSharedMemorySize, FA_SMEM_BYTES);

    dim3 gg(Dn / 128, Mn / 128);   // (16, 32)

    sgemm_nt_bias<<<gg, 256>>>(x, q_w, q_b, pQ, Mn, Dn, Dn);
    sgemm_nt_bias<<<gg, 256>>>(x, k_w, k_b, pK, Mn, Dn, Dn);
    sgemm_nt_bias<<<gg, 256>>>(x, v_w, v_b, pV, Mn, Dn, Dn);

    rope_table_kernel<<<(Sn * 64 + 255) / 256, 256>>>();
    rope_apply_kernel<<<(Bn * Sn * Hn * 64 + 255) / 256, 256>>>(pQ);
    rope_apply_kernel<<<(Bn * Sn * Hn * 64 + 255) / 256, 256>>>(pK);

    flash_attn_kernel<<<dim3(Sn / 64, Bn * Hn), 256, FA_SMEM_BYTES>>>(pQ, pK, pV, pO);

    sgemm_nt_bias<<<gg, 256>>>(pO, out_w, out_b, out, Mn, Dn, Dn);
}

// round 3
// speedup vs baseline: 1.4263x; 1.4263x over previous
#include <cuda_runtime.h>
#include <cuda_bf16.h>
#include <cstdint>
#include <math.h>

// Problem constants
#define Bn  2
#define Sn  2048
#define Dn  2048
#define Hn  16
#define DHn 128
#define Mn  (Bn*Sn)          // 4096 rows for all GEMMs

// ---------------------------------------------------------------------------
// Scratch (no allocation allowed -> __device__ globals)
// ---------------------------------------------------------------------------
__device__ float g_Q[(size_t)Mn*Dn];
__device__ float g_K[(size_t)Mn*Dn];
__device__ float g_V[(size_t)Mn*Dn];
__device__ float g_O[(size_t)Mn*Dn];
__device__ float g_ct[Sn*64];
__device__ float g_st[Sn*64];

// bf16 split copies
__device__ __nv_bfloat16 g_xh[(size_t)Mn*Dn],  g_xl[(size_t)Mn*Dn];
__device__ __nv_bfloat16 g_Oh[(size_t)Mn*Dn],  g_Ol[(size_t)Mn*Dn];
__device__ __nv_bfloat16 g_qwh[(size_t)Dn*Dn], g_qwl[(size_t)Dn*Dn];
__device__ __nv_bfloat16 g_kwh[(size_t)Dn*Dn], g_kwl[(size_t)Dn*Dn];
__device__ __nv_bfloat16 g_vwh[(size_t)Dn*Dn], g_vwl[(size_t)Dn*Dn];
__device__ __nv_bfloat16 g_owh[(size_t)Dn*Dn], g_owl[(size_t)Dn*Dn];

__device__ __forceinline__ uint32_t smem_u32(const void* p) {
    uint32_t a;
    asm("{ .reg .u64 t; cvta.to.shared.u64 t, %1; cvt.u32.u64 %0, t; }"
        : "=r"(a) : "l"(p));
    return a;
}

// ---------------------------------------------------------------------------
// bf16 split conversion: hi = bf16(v), lo = bf16(v - hi)
// ---------------------------------------------------------------------------
__global__ void split_bf16_kernel(const float* __restrict__ src,
                                  __nv_bfloat16* __restrict__ hi,
                                  __nv_bfloat16* __restrict__ lo, int n4)
{
    int i = blockIdx.x * blockDim.x + threadIdx.x;
    if (i >= n4) return;
    float4 v = ((const float4*)src)[i];
    __nv_bfloat16 h0 = __float2bfloat16(v.x);
    __nv_bfloat16 h1 = __float2bfloat16(v.y);
    __nv_bfloat16 h2 = __float2bfloat16(v.z);
    __nv_bfloat16 h3 = __float2bfloat16(v.w);
    __nv_bfloat162 hh0, hh1, ll0, ll1;
    hh0.x = h0; hh0.y = h1; hh1.x = h2; hh1.y = h3;
    ll0.x = __float2bfloat16(v.x - __bfloat162float(h0));
    ll0.y = __float2bfloat16(v.y - __bfloat162float(h1));
    ll1.x = __float2bfloat16(v.z - __bfloat162float(h2));
    ll1.y = __float2bfloat16(v.w - __bfloat162float(h3));
    ((__nv_bfloat162*)hi)[i*2]   = hh0;
    ((__nv_bfloat162*)hi)[i*2+1] = hh1;
    ((__nv_bfloat162*)lo)[i*2]   = ll0;
    ((__nv_bfloat162*)lo)[i*2+1] = ll1;
}

// ---------------------------------------------------------------------------
// Split-bf16 GEMM on tensor cores via mma.sync m16n8k16 (sm_80+ path).
// C[m,n] = sum_k A[m,k]*W[n,k] + bias[n], fp32 out.
// C = AhWh + AlWh + AhWl accumulated over 3 K-segments of 2048.
// Tile 128x128, BK=32 bf16, 8 warps (each 64x32), double-buffered smem.
// smem rows: 32 bf16 = 64B data, 80B stride (conflict-free ldmatrix).
// ---------------------------------------------------------------------------
#define GK       2048
#define NCHUNK   192               // 3 segments * 64 chunks of BK=32
#define TILE_BYTES 10240           // 128 rows * 80B
#define BUF_BYTES  (2*TILE_BYTES)  // A + B

__global__ __launch_bounds__(256, 2) void gemm_mma(
    const __nv_bfloat16* __restrict__ Ah, const __nv_bfloat16* __restrict__ Al,
    const __nv_bfloat16* __restrict__ Wh, const __nv_bfloat16* __restrict__ Wl,
    const float* __restrict__ bias, float* __restrict__ C)
{
    __shared__ __align__(16) char smem[2 * BUF_BYTES];   // 40960 B

    const int tid = threadIdx.x;
    const int lid = tid & 31;
    const int wid = tid >> 5;
    const int wm  = wid & 1;         // 2 warp-rows of 64
    const int wn  = wid >> 1;        // 4 warp-cols of 32
    const int bn  = blockIdx.x * 128;
    const int bm  = blockIdx.y * 128;
    const uint32_t sb = smem_u32(smem);

    // global load indices: 512 16B-chunks per operand tile, 2 per thread
    const int gr = tid >> 2;         // row 0..63   (and +64)
    const int gc = (tid & 3) * 8;    // element offset 0,8,16,24

    float acc[4][4][4];
#pragma unroll
    for (int a = 0; a < 4; a++)
#pragma unroll
        for (int b = 0; b < 4; b++)
#pragma unroll
            for (int c = 0; c < 4; c++) acc[a][b][c] = 0.f;

    uint4 pa0, pa1, pb0, pb1;

    auto gload = [&](int ci) {
        int seg = ci >> 6;
        int k0  = (ci & 63) << 5;
        const __nv_bfloat16* As = (seg == 1) ? Al : Ah;
        const __nv_bfloat16* Ws = (seg == 2) ? Wl : Wh;
        pa0 = *(const uint4*)(As + (size_t)(bm + gr)      * GK + k0 + gc);
        pa1 = *(const uint4*)(As + (size_t)(bm + gr + 64) * GK + k0 + gc);
        pb0 = *(const uint4*)(Ws + (size_t)(bn + gr)      * GK + k0 + gc);
        pb1 = *(const uint4*)(Ws + (size_t)(bn + gr + 64) * GK + k0 + gc);
    };
    auto sstore = [&](int buf) {
        char* base = smem + buf * BUF_BYTES;
        *(uint4*)(base + gr * 80        + gc * 2) = pa0;
        *(uint4*)(base + (gr + 64) * 80 + gc * 2) = pa1;
        char* bb = base + TILE_BYTES;
        *(uint4*)(bb + gr * 80        + gc * 2) = pb0;
        *(uint4*)(bb + (gr + 64) * 80 + gc * 2) = pb1;
    };

    // per-lane ldmatrix base addresses (element k=0, buffer 0)
    const uint32_t a_base = sb + (uint32_t)(wm * 64 + (lid & 15)) * 80
                          + ((lid >> 4) << 4);
    const uint32_t b_base = sb + TILE_BYTES
                          + (uint32_t)(wn * 32 + ((lid >> 4) << 3) + (lid & 7)) * 80
                          + (((lid >> 3) & 1) << 4);

    gload(0);
    sstore(0);
    __syncthreads();

    for (int i = 0; i < NCHUNK; i++) {
        const int cur = i & 1;
        if (i + 1 < NCHUNK) gload(i + 1);

        const uint32_t abuf = a_base + cur * BUF_BYTES;
        const uint32_t bbuf = b_base + cur * BUF_BYTES;
#pragma unroll
        for (int k16 = 0; k16 < 2; k16++) {
            uint32_t af[4][4], bf[4][2];
#pragma unroll
            for (int mi = 0; mi < 4; mi++) {
                uint32_t ad = abuf + mi * (16 * 80) + k16 * 32;
                asm volatile("ldmatrix.sync.aligned.m8n8.x4.shared.b16 "
                             "{%0,%1,%2,%3}, [%4];"
                             : "=r"(af[mi][0]), "=r"(af[mi][1]),
                               "=r"(af[mi][2]), "=r"(af[mi][3])
                             : "r"(ad));
            }
#pragma unroll
            for (int nj = 0; nj < 2; nj++) {
                uint32_t bd = bbuf + nj * (16 * 80) + k16 * 32;
                asm volatile("ldmatrix.sync.aligned.m8n8.x4.shared.b16 "
                             "{%0,%1,%2,%3}, [%4];"
                             : "=r"(bf[2*nj][0]),   "=r"(bf[2*nj][1]),
                               "=r"(bf[2*nj+1][0]), "=r"(bf[2*nj+1][1])
                             : "r"(bd));
            }
#pragma unroll
            for (int mi = 0; mi < 4; mi++)
#pragma unroll
                for (int ni = 0; ni < 4; ni++) {
                    asm volatile(
                        "mma.sync.aligned.m16n8k16.row.col.f32.bf16.bf16.f32 "
                        "{%0,%1,%2,%3}, {%4,%5,%6,%7}, {%8,%9}, {%0,%1,%2,%3};"
                        : "+f"(acc[mi][ni][0]), "+f"(acc[mi][ni][1]),
                          "+f"(acc[mi][ni][2]), "+f"(acc[mi][ni][3])
                        : "r"(af[mi][0]), "r"(af[mi][1]),
                          "r"(af[mi][2]), "r"(af[mi][3]),
                          "r"(bf[ni][0]), "r"(bf[ni][1]));
                }
        }

        if (i + 1 < NCHUNK) sstore(cur ^ 1);
        __syncthreads();
    }

    // ---- epilogue ----
    const int g   = lid >> 2;
    const int tg2 = (lid & 3) * 2;
#pragma unroll
    for (int ni = 0; ni < 4; ni++) {
        const int col = bn + wn * 32 + ni * 8 + tg2;
        const float b0 = bias[col], b1 = bias[col + 1];
#pragma unroll
        for (int mi = 0; mi < 4; mi++) {
            const int row = bm + wm * 64 + mi * 16 + g;
            float2 v0 = make_float2(acc[mi][ni][0] + b0, acc[mi][ni][1] + b1);
            float2 v1 = make_float2(acc[mi][ni][2] + b0, acc[mi][ni][3] + b1);
            *(float2*)(C + (size_t)row * Dn + col)       = v0;
            *(float2*)(C + (size_t)(row + 8) * Dn + col) = v1;
        }
    }
}

// ---------------------------------------------------------------------------
// RoPE cos/sin table in fp64 (exact angles)
// ---------------------------------------------------------------------------
__global__ void rope_table_kernel()
{
    int idx = blockIdx.x * blockDim.x + threadIdx.x;
    if (idx >= Sn * 64) return;
    int i = idx & 63;
    int s = idx >> 6;
    double inv = exp((double)(-2 * i) * (9.210340371976182736 / 128.0)); // ln(1e4)
    double ang = (double)s * inv;
    g_ct[idx] = (float)cos(ang);
    g_st[idx] = (float)sin(ang);
}

// ---------------------------------------------------------------------------
// RoPE apply (in-place), pair (i, i+64) within each head
// ---------------------------------------------------------------------------
__global__ void rope_apply_kernel(float* __restrict__ X)
{
    int idx = blockIdx.x * blockDim.x + threadIdx.x;
    if (idx >= Bn * Sn * Hn * 64) return;
    int i = idx & 63;
    int h = (idx >> 6) & (Hn - 1);
    int s = (idx >> 10) & (Sn - 1);
    int b = idx >> 21;
    size_t base = (size_t)(b * Sn + s) * Dn + h * DHn;
    float c  = g_ct[(s << 6) | i];
    float sv = g_st[(s << 6) | i];
    float x1 = X[base + i];
    float x2 = X[base + 64 + i];
    X[base + i]      = x1 * c - x2 * sv;
    X[base + 64 + i] = x2 * c + x1 * sv;
}

// ---------------------------------------------------------------------------
// Flash attention, fp32 (unchanged from R1; passes at rel_err 1e-5)
// ---------------------------------------------------------------------------
#define FA_SMEM_FLOATS (128*68 + 128*68 + 64*68)
#define FA_SMEM_BYTES  (FA_SMEM_FLOATS * 4)

__global__ __launch_bounds__(256) void flash_attn_kernel(
    const float* __restrict__ Q, const float* __restrict__ K,
    const float* __restrict__ V, float* __restrict__ O)
{
    extern __shared__ float sm[];
    float* sQ  = sm;
    float* sKV = sm + 128 * 68;
    float* sP  = sm + 2 * 128 * 68;

    const int tid = threadIdx.x;
    const int tx  = tid & 15;
    const int ty  = tid >> 4;
    const int qt  = blockIdx.x;
    const int bh  = blockIdx.y;
    const int b   = bh >> 4;
    const int h   = bh & 15;

    const float scale = 0.088388347648318447f;

    {
        const int d4 = tid & 31;
        const int r0 = tid >> 5;
#pragma unroll
        for (int i = 0; i < 8; i++) {
            int r = r0 + i * 8;
            float4 v4 = *(const float4*)(Q + ((size_t)(b * Sn + qt * 64 + r) * Dn
                                              + h * DHn + d4 * 4));
            sQ[(d4 * 4 + 0) * 68 + r] = v4.x * scale;
            sQ[(d4 * 4 + 1) * 68 + r] = v4.y * scale;
            sQ[(d4 * 4 + 2) * 68 + r] = v4.z * scale;
            sQ[(d4 * 4 + 3) * 68 + r] = v4.w * scale;
        }
    }

    float m_i[4], l_i[4], acc[4][8];
#pragma unroll
    for (int i = 0; i < 4; i++) {
        m_i[i] = -1e30f;
        l_i[i] = 0.f;
#pragma unroll
        for (int j = 0; j < 8; j++) acc[i][j] = 0.f;
    }

    for (int jt = 0; jt < Sn / 64; jt++) {
        {
            const int d4 = tid & 31;
            const int c0 = tid >> 5;
#pragma unroll
            for (int i = 0; i < 8; i++) {
                int c = c0 + i * 8;
                float4 v4 = *(const float4*)(K + ((size_t)(b * Sn + jt * 64 + c) * Dn
                                                  + h * DHn + d4 * 4));
                sKV[(d4 * 4 + 0) * 68 + c] = v4.x;
                sKV[(d4 * 4 + 1) * 68 + c] = v4.y;
                sKV[(d4 * 4 + 2) * 68 + c] = v4.z;
                sKV[(d4 * 4 + 3) * 68 + c] = v4.w;
            }
        }
        __syncthreads();

        float s_acc[4][4];
#pragma unroll
        for (int i = 0; i < 4; i++)
#pragma unroll
            for (int j = 0; j < 4; j++) s_acc[i][j] = 0.f;

#pragma unroll 8
        for (int d = 0; d < 128; d++) {
            float4 qa = *(const float4*)&sQ[d * 68 + ty * 4];
            float4 kb = *(const float4*)&sKV[d * 68 + tx * 4];
            float qr[4] = {qa.x, qa.y, qa.z, qa.w};
            float kr[4] = {kb.x, kb.y, kb.z, kb.w};
#pragma unroll
            for (int i = 0; i < 4; i++)
#pragma unroll
                for (int j = 0; j < 4; j++)
                    s_acc[i][j] = fmaf(qr[i], kr[j], s_acc[i][j]);
        }
        __syncthreads();

        float rmax[4];
#pragma unroll
        for (int i = 0; i < 4; i++) {
            rmax[i] = s_acc[i][0];
#pragma unroll
            for (int j = 1; j < 4; j++) rmax[i] = fmaxf(rmax[i], s_acc[i][j]);
        }
#pragma unroll
        for (int off = 8; off > 0; off >>= 1)
#pragma unroll
            for (int i = 0; i < 4; i++)
                rmax[i] = fmaxf(rmax[i], __shfl_xor_sync(0xffffffffu, rmax[i], off));

        float psum[4];
#pragma unroll
        for (int i = 0; i < 4; i++) {
            float mn  = fmaxf(m_i[i], rmax[i]);
            float cor = __expf(m_i[i] - mn);
            m_i[i] = mn;
            l_i[i] *= cor;
#pragma unroll
            for (int jj = 0; jj < 8; jj++) acc[i][jj] *= cor;
            float ps = 0.f;
#pragma unroll
            for (int j = 0; j < 4; j++) {
                float p = __expf(s_acc[i][j] - mn);
                sP[(tx * 4 + j) * 68 + (ty * 4 + i)] = p;
                ps += p;
            }
            psum[i] = ps;
        }
#pragma unroll
        for (int off = 8; off > 0; off >>= 1)
#pragma unroll
            for (int i = 0; i < 4; i++)
                psum[i] += __shfl_xor_sync(0xffffffffu, psum[i], off);
#pragma unroll
        for (int i = 0; i < 4; i++) l_i[i] += psum[i];

        {
            const int d4 = tid & 31;
            const int c0 = tid >> 5;
#pragma unroll
            for (int i = 0; i < 8; i++) {
                int c = c0 + i * 8;
                float4 v4 = *(const float4*)(V + ((size_t)(b * Sn + jt * 64 + c) * Dn
                                                  + h * DHn + d4 * 4));
                *(float4*)&sKV[c * 128 + d4 * 4] = v4;
            }
        }
        __syncthreads();

#pragma unroll 4
        for (int c = 0; c < 64; c++) {
            float4 pa = *(const float4*)&sP[c * 68 + ty * 4];
            float4 v0 = *(const float4*)&sKV[c * 128 + tx * 8];
            float4 v1 = *(const float4*)&sKV[c * 128 + tx * 8 + 4];
            float pr[4] = {pa.x, pa.y, pa.z, pa.w};
            float vr[8] = {v0.x, v0.y, v0.z, v0.w, v1.x, v1.y, v1.z, v1.w};
#pragma unroll
            for (int i = 0; i < 4; i++)
#pragma unroll
                for (int jj = 0; jj < 8; jj++)
                    acc[i][jj] = fmaf(pr[i], vr[jj], acc[i][jj]);
        }
        __syncthreads();
    }

#pragma unroll
    for (int i = 0; i < 4; i++) {
        float inv_l = 1.f / l_i[i];
        size_t row = (size_t)(b * Sn + qt * 64 + ty * 4 + i) * Dn + h * DHn + tx * 8;
        float4 o0 = make_float4(acc[i][0] * inv_l, acc[i][1] * inv_l,
                                acc[i][2] * inv_l, acc[i][3] * inv_l);
        float4 o1 = make_float4(acc[i][4] * inv_l, acc[i][5] * inv_l,
                                acc[i][6] * inv_l, acc[i][7] * inv_l);
        *(float4*)&O[row]     = o0;
        *(float4*)&O[row + 4] = o1;
    }
}

// ---------------------------------------------------------------------------
// Launch
// ---------------------------------------------------------------------------
extern "C" void kernel_launch(void* const* d_in, const int* in_sizes, int n_in,
                              void* d_out, int out_size)
{
    const float* x     = (const float*)d_in[0];
    const float* q_w   = (const float*)d_in[1];
    const float* k_w   = (const float*)d_in[2];
    const float* v_w   = (const float*)d_in[3];
    const float* q_b   = (const float*)d_in[4];
    const float* k_b   = (const float*)d_in[5];
    const float* v_b   = (const float*)d_in[6];
    const float* out_w = (const float*)d_in[7];
    const float* out_b = (const float*)d_in[8];
    float* out = (float*)d_out;

    float *pQ, *pK, *pV, *pO;
    cudaGetSymbolAddress((void**)&pQ, g_Q);
    cudaGetSymbolAddress((void**)&pK, g_K);
    cudaGetSymbolAddress((void**)&pV, g_V);
    cudaGetSymbolAddress((void**)&pO, g_O);

    __nv_bfloat16 *xh, *xl, *Oh, *Ol, *qwh, *qwl, *kwh, *kwl, *vwh, *vwl, *owh, *owl;
    cudaGetSymbolAddress((void**)&xh,  g_xh);  cudaGetSymbolAddress((void**)&xl,  g_xl);
    cudaGetSymbolAddress((void**)&Oh,  g_Oh);  cudaGetSymbolAddress((void**)&Ol,  g_Ol);
    cudaGetSymbolAddress((void**)&qwh, g_qwh); cudaGetSymbolAddress((void**)&qwl, g_qwl);
    cudaGetSymbolAddress((void**)&kwh, g_kwh); cudaGetSymbolAddress((void**)&kwl, g_kwl);
    cudaGetSymbolAddress((void**)&vwh, g_vwh); cudaGetSymbolAddress((void**)&vwl, g_vwl);
    cudaGetSymbolAddress((void**)&owh, g_owh); cudaGetSymbolAddress((void**)&owl, g_owl);

    cudaFuncSetAttribute(flash_attn_kernel,
                         cudaFuncAttributeMaxDynamicSharedMemorySize, FA_SMEM_BYTES);

    const int nx4 = Mn * Dn / 4;   // float4 count
    const int nw4 = Dn * Dn / 4;

    split_bf16_kernel<<<(nx4 + 255) / 256, 256>>>(x,     xh,  xl,  nx4);
    split_bf16_kernel<<<(nw4 + 255) / 256, 256>>>(q_w,   qwh, qwl, nw4);
    split_bf16_kernel<<<(nw4 + 255) / 256, 256>>>(k_w,   kwh, kwl, nw4);
    split_bf16_kernel<<<(nw4 + 255) / 256, 256>>>(v_w,   vwh, vwl, nw4);
    split_bf16_kernel<<<(nw4 + 255) / 256, 256>>>(out_w, owh, owl, nw4);

    dim3 gg(Dn / 128, Mn / 128);   // (16, 32)
    gemm_mma<<<gg, 256>>>(xh, xl, qwh, qwl, q_b, pQ);
    gemm_mma<<<gg, 256>>>(xh, xl, kwh, kwl, k_b, pK);
    gemm_mma<<<gg, 256>>>(xh, xl, vwh, vwl, v_b, pV);

    rope_table_kernel<<<(Sn * 64 + 255) / 256, 256>>>();
    rope_apply_kernel<<<(Bn * Sn * Hn * 64 + 255) / 256, 256>>>(pQ);
    rope_apply_kernel<<<(Bn * Sn * Hn * 64 + 255) / 256, 256>>>(pK);

    flash_attn_kernel<<<dim3(Sn / 64, Bn * Hn), 256, FA_SMEM_BYTES>>>(pQ, pK, pV, pO);

    split_bf16_kernel<<<(nx4 + 255) / 256, 256>>>(pO, Oh, Ol, nx4);
    gemm_mma<<<gg, 256>>>(Oh, Ol, owh, owl, out_b, out);
}

// round 4
// speedup vs baseline: 1.4644x; 1.0266x over previous
#include <cuda_runtime.h>
#include <cuda_bf16.h>
#include <cstdint>
#include <math.h>

// Problem constants
#define Bn  2
#define Sn  2048
#define Dn  2048
#define Hn  16
#define DHn 128
#define Mn  (Bn*Sn)          // 4096 rows for all GEMMs

// ---------------------------------------------------------------------------
// Scratch (no allocation allowed -> __device__ globals)
// ---------------------------------------------------------------------------
__device__ float g_Q[(size_t)Mn*Dn];
__device__ float g_K[(size_t)Mn*Dn];
__device__ float g_V[(size_t)Mn*Dn];
__device__ float g_O[(size_t)Mn*Dn];
__device__ float g_ct[Sn*64];
__device__ float g_st[Sn*64];

// bf16 split copies
__device__ __nv_bfloat16 g_xh[(size_t)Mn*Dn],  g_xl[(size_t)Mn*Dn];
__device__ __nv_bfloat16 g_Oh[(size_t)Mn*Dn],  g_Ol[(size_t)Mn*Dn];
__device__ __nv_bfloat16 g_qwh[(size_t)Dn*Dn], g_qwl[(size_t)Dn*Dn];
__device__ __nv_bfloat16 g_kwh[(size_t)Dn*Dn], g_kwl[(size_t)Dn*Dn];
__device__ __nv_bfloat16 g_vwh[(size_t)Dn*Dn], g_vwl[(size_t)Dn*Dn];
__device__ __nv_bfloat16 g_owh[(size_t)Dn*Dn], g_owl[(size_t)Dn*Dn];

__device__ __forceinline__ uint32_t smem_u32(const void* p) {
    uint32_t a;
    asm("{ .reg .u64 t; cvta.to.shared.u64 t, %1; cvt.u32.u64 %0, t; }"
        : "=r"(a) : "l"(p));
    return a;
}

#define CP_ASYNC16(smem_addr, gptr) \
    asm volatile("cp.async.cg.shared.global [%0], [%1], 16;" \
                 :: "r"(smem_addr), "l"(gptr) : "memory")
#define CP_COMMIT()  asm volatile("cp.async.commit_group;" ::: "memory")
#define CP_WAIT2()   asm volatile("cp.async.wait_group 2;"  ::: "memory")

// ---------------------------------------------------------------------------
// bf16 split conversion: hi = bf16(v), lo = bf16(v - hi)
// ---------------------------------------------------------------------------
__global__ void split_bf16_kernel(const float* __restrict__ src,
                                  __nv_bfloat16* __restrict__ hi,
                                  __nv_bfloat16* __restrict__ lo, int n4)
{
    int i = blockIdx.x * blockDim.x + threadIdx.x;
    if (i >= n4) return;
    float4 v = ((const float4*)src)[i];
    __nv_bfloat16 h0 = __float2bfloat16(v.x);
    __nv_bfloat16 h1 = __float2bfloat16(v.y);
    __nv_bfloat16 h2 = __float2bfloat16(v.z);
    __nv_bfloat16 h3 = __float2bfloat16(v.w);
    __nv_bfloat162 hh0, hh1, ll0, ll1;
    hh0.x = h0; hh0.y = h1; hh1.x = h2; hh1.y = h3;
    ll0.x = __float2bfloat16(v.x - __bfloat162float(h0));
    ll0.y = __float2bfloat16(v.y - __bfloat162float(h1));
    ll1.x = __float2bfloat16(v.z - __bfloat162float(h2));
    ll1.y = __float2bfloat16(v.w - __bfloat162float(h3));
    ((__nv_bfloat162*)hi)[i*2]   = hh0;
    ((__nv_bfloat162*)hi)[i*2+1] = hh1;
    ((__nv_bfloat162*)lo)[i*2]   = ll0;
    ((__nv_bfloat162*)lo)[i*2+1] = ll1;
}

// ---------------------------------------------------------------------------
// Split-bf16 GEMM on tensor cores via mma.sync m16n8k16, cp.async 4-stage
// pipeline. C[m,n] = sum_k A[m,k]*W[n,k] + bias[n], fp32 out.
// C = AhWh + AlWh + AhWl over 3 K-segments of 2048.
// Tile 128x128, BK=32 bf16, 8 warps (each 64x32).
// smem rows: 32 bf16 = 64B data, 80B stride (conflict-free ldmatrix).
// ---------------------------------------------------------------------------
#define GK       2048
#define NCHUNK   192               // 3 segments * 64 chunks of BK=32
#define TILE_BYTES  10240          // 128 rows * 80B
#define STAGE_BYTES (2*TILE_BYTES) // A + B
#define STAGES   4
#define GEMM_SMEM (STAGES*STAGE_BYTES)   // 81920

__global__ __launch_bounds__(256, 2) void gemm_mma(
    const __nv_bfloat16* __restrict__ Ah, const __nv_bfloat16* __restrict__ Al,
    const __nv_bfloat16* __restrict__ Wh, const __nv_bfloat16* __restrict__ Wl,
    const float* __restrict__ bias, float* __restrict__ C)
{
    extern __shared__ __align__(16) char smem[];

    const int tid = threadIdx.x;
    const int lid = tid & 31;
    const int wid = tid >> 5;
    const int wm  = wid & 1;         // 2 warp-rows of 64
    const int wn  = wid >> 1;        // 4 warp-cols of 32
    const int bn  = blockIdx.x * 128;
    const int bm  = blockIdx.y * 128;
    const uint32_t sb = smem_u32(smem);

    // global load indices: per thread 2 chunks for A + 2 for B
    const int gr = tid >> 2;         // row 0..63   (and +64)
    const int gc = (tid & 3) * 8;    // element offset 0,8,16,24

    const uint32_t sA0 = sb + (uint32_t)(gr * 80 + gc * 2);
    const uint32_t sA1 = sA0 + 64 * 80;
    const uint32_t sB0 = sA0 + TILE_BYTES;
    const uint32_t sB1 = sA1 + TILE_BYTES;

    float acc[4][4][4];
#pragma unroll
    for (int a = 0; a < 4; a++)
#pragma unroll
        for (int b = 0; b < 4; b++)
#pragma unroll
            for (int c = 0; c < 4; c++) acc[a][b][c] = 0.f;

    auto issue = [&](int ci) {
        int seg = ci >> 6;
        int k0  = (ci & 63) << 5;
        const __nv_bfloat16* As = (seg == 1) ? Al : Ah;
        const __nv_bfloat16* Ws = (seg == 2) ? Wl : Wh;
        uint32_t off = (uint32_t)(ci & (STAGES - 1)) * STAGE_BYTES;
        CP_ASYNC16(sA0 + off, As + (size_t)(bm + gr)      * GK + k0 + gc);
        CP_ASYNC16(sA1 + off, As + (size_t)(bm + gr + 64) * GK + k0 + gc);
        CP_ASYNC16(sB0 + off, Ws + (size_t)(bn + gr)      * GK + k0 + gc);
        CP_ASYNC16(sB1 + off, Ws + (size_t)(bn + gr + 64) * GK + k0 + gc);
        CP_COMMIT();
    };

    // per-lane ldmatrix base addresses (k=0, stage 0)
    const uint32_t a_base = sb + (uint32_t)(wm * 64 + (lid & 15)) * 80
                          + ((lid >> 4) << 4);
    const uint32_t b_base = sb + TILE_BYTES
                          + (uint32_t)(wn * 32 + ((lid >> 4) << 3) + (lid & 7)) * 80
                          + (((lid >> 3) & 1) << 4);

    issue(0); issue(1); issue(2);

    for (int i = 0; i < NCHUNK; i++) {
        CP_WAIT2();
        __syncthreads();
        if (i + 3 < NCHUNK) issue(i + 3);

        const uint32_t off  = (uint32_t)(i & (STAGES - 1)) * STAGE_BYTES;
        const uint32_t abuf = a_base + off;
        const uint32_t bbuf = b_base + off;
#pragma unroll
        for (int k16 = 0; k16 < 2; k16++) {
            uint32_t af[4][4], bf[4][2];
#pragma unroll
            for (int mi = 0; mi < 4; mi++) {
                uint32_t ad = abuf + mi * (16 * 80) + k16 * 32;
                asm volatile("ldmatrix.sync.aligned.m8n8.x4.shared.b16 "
                             "{%0,%1,%2,%3}, [%4];"
                             : "=r"(af[mi][0]), "=r"(af[mi][1]),
                               "=r"(af[mi][2]), "=r"(af[mi][3])
                             : "r"(ad));
            }
#pragma unroll
            for (int nj = 0; nj < 2; nj++) {
                uint32_t bd = bbuf + nj * (16 * 80) + k16 * 32;
                asm volatile("ldmatrix.sync.aligned.m8n8.x4.shared.b16 "
                             "{%0,%1,%2,%3}, [%4];"
                             : "=r"(bf[2*nj][0]),   "=r"(bf[2*nj][1]),
                               "=r"(bf[2*nj+1][0]), "=r"(bf[2*nj+1][1])
                             : "r"(bd));
            }
#pragma unroll
            for (int mi = 0; mi < 4; mi++)
#pragma unroll
                for (int ni = 0; ni < 4; ni++) {
                    asm volatile(
                        "mma.sync.aligned.m16n8k16.row.col.f32.bf16.bf16.f32 "
                        "{%0,%1,%2,%3}, {%4,%5,%6,%7}, {%8,%9}, {%0,%1,%2,%3};"
                        : "+f"(acc[mi][ni][0]), "+f"(acc[mi][ni][1]),
                          "+f"(acc[mi][ni][2]), "+f"(acc[mi][ni][3])
                        : "r"(af[mi][0]), "r"(af[mi][1]),
                          "r"(af[mi][2]), "r"(af[mi][3]),
                          "r"(bf[ni][0]), "r"(bf[ni][1]));
                }
        }
    }

    // ---- epilogue ----
    const int g   = lid >> 2;
    const int tg2 = (lid & 3) * 2;
#pragma unroll
    for (int ni = 0; ni < 4; ni++) {
        const int col = bn + wn * 32 + ni * 8 + tg2;
        const float b0 = bias[col], b1 = bias[col + 1];
#pragma unroll
        for (int mi = 0; mi < 4; mi++) {
            const int row = bm + wm * 64 + mi * 16 + g;
            float2 v0 = make_float2(acc[mi][ni][0] + b0, acc[mi][ni][1] + b1);
            float2 v1 = make_float2(acc[mi][ni][2] + b0, acc[mi][ni][3] + b1);
            *(float2*)(C + (size_t)row * Dn + col)       = v0;
            *(float2*)(C + (size_t)(row + 8) * Dn + col) = v1;
        }
    }
}

// ---------------------------------------------------------------------------
// RoPE cos/sin table in fp64 (exact angles)
// ---------------------------------------------------------------------------
__global__ void rope_table_kernel()
{
    int idx = blockIdx.x * blockDim.x + threadIdx.x;
    if (idx >= Sn * 64) return;
    int i = idx & 63;
    int s = idx >> 6;
    double inv = exp((double)(-2 * i) * (9.210340371976182736 / 128.0)); // ln(1e4)
    double ang = (double)s * inv;
    g_ct[idx] = (float)cos(ang);
    g_st[idx] = (float)sin(ang);
}

// ---------------------------------------------------------------------------
// RoPE apply (in-place), pair (i, i+64) within each head
// ---------------------------------------------------------------------------
__global__ void rope_apply_kernel(float* __restrict__ X)
{
    int idx = blockIdx.x * blockDim.x + threadIdx.x;
    if (idx >= Bn * Sn * Hn * 64) return;
    int i = idx & 63;
    int h = (idx >> 6) & (Hn - 1);
    int s = (idx >> 10) & (Sn - 1);
    int b = idx >> 21;
    size_t base = (size_t)(b * Sn + s) * Dn + h * DHn;
    float c  = g_ct[(s << 6) | i];
    float sv = g_st[(s << 6) | i];
    float x1 = X[base + i];
    float x2 = X[base + 64 + i];
    X[base + i]      = x1 * c - x2 * sv;
    X[base + 64 + i] = x2 * c + x1 * sv;
}

// ---------------------------------------------------------------------------
// Flash attention, fp32 (unchanged; passes at rel_err 1e-5)
// ---------------------------------------------------------------------------
#define FA_SMEM_FLOATS (128*68 + 128*68 + 64*68)
#define FA_SMEM_BYTES  (FA_SMEM_FLOATS * 4)

__global__ __launch_bounds__(256) void flash_attn_kernel(
    const float* __restrict__ Q, const float* __restrict__ K,
    const float* __restrict__ V, float* __restrict__ O)
{
    extern __shared__ float sm[];
    float* sQ  = sm;
    float* sKV = sm + 128 * 68;
    float* sP  = sm + 2 * 128 * 68;

    const int tid = threadIdx.x;
    const int tx  = tid & 15;
    const int ty  = tid >> 4;
    const int qt  = blockIdx.x;
    const int bh  = blockIdx.y;
    const int b   = bh >> 4;
    const int h   = bh & 15;

    const float scale = 0.088388347648318447f;

    {
        const int d4 = tid & 31;
        const int r0 = tid >> 5;
#pragma unroll
        for (int i = 0; i < 8; i++) {
            int r = r0 + i * 8;
            float4 v4 = *(const float4*)(Q + ((size_t)(b * Sn + qt * 64 + r) * Dn
                                              + h * DHn + d4 * 4));
            sQ[(d4 * 4 + 0) * 68 + r] = v4.x * scale;
            sQ[(d4 * 4 + 1) * 68 + r] = v4.y * scale;
            sQ[(d4 * 4 + 2) * 68 + r] = v4.z * scale;
            sQ[(d4 * 4 + 3) * 68 + r] = v4.w * scale;
        }
    }

    float m_i[4], l_i[4], acc[4][8];
#pragma unroll
    for (int i = 0; i < 4; i++) {
        m_i[i] = -1e30f;
        l_i[i] = 0.f;
#pragma unroll
        for (int j = 0; j < 8; j++) acc[i][j] = 0.f;
    }

    for (int jt = 0; jt < Sn / 64; jt++) {
        {
            const int d4 = tid & 31;
            const int c0 = tid >> 5;
#pragma unroll
            for (int i = 0; i < 8; i++) {
                int c = c0 + i * 8;
                float4 v4 = *(const float4*)(K + ((size_t)(b * Sn + jt * 64 + c) * Dn
                                                  + h * DHn + d4 * 4));
                sKV[(d4 * 4 + 0) * 68 + c] = v4.x;
                sKV[(d4 * 4 + 1) * 68 + c] = v4.y;
                sKV[(d4 * 4 + 2) * 68 + c] = v4.z;
                sKV[(d4 * 4 + 3) * 68 + c] = v4.w;
            }
        }
        __syncthreads();

        float s_acc[4][4];
#pragma unroll
        for (int i = 0; i < 4; i++)
#pragma unroll
            for (int j = 0; j < 4; j++) s_acc[i][j] = 0.f;

#pragma unroll 8
        for (int d = 0; d < 128; d++) {
            float4 qa = *(const float4*)&sQ[d * 68 + ty * 4];
            float4 kb = *(const float4*)&sKV[d * 68 + tx * 4];
            float qr[4] = {qa.x, qa.y, qa.z, qa.w};
            float kr[4] = {kb.x, kb.y, kb.z, kb.w};
#pragma unroll
            for (int i = 0; i < 4; i++)
#pragma unroll
                for (int j = 0; j < 4; j++)
                    s_acc[i][j] = fmaf(qr[i], kr[j], s_acc[i][j]);
        }
        __syncthreads();

        float rmax[4];
#pragma unroll
        for (int i = 0; i < 4; i++) {
            rmax[i] = s_acc[i][0];
#pragma unroll
            for (int j = 1; j < 4; j++) rmax[i] = fmaxf(rmax[i], s_acc[i][j]);
        }
#pragma unroll
        for (int off = 8; off > 0; off >>= 1)
#pragma unroll
            for (int i = 0; i < 4; i++)
                rmax[i] = fmaxf(rmax[i], __shfl_xor_sync(0xffffffffu, rmax[i], off));

        float psum[4];
#pragma unroll
        for (int i = 0; i < 4; i++) {
            float mn  = fmaxf(m_i[i], rmax[i]);
            float cor = __expf(m_i[i] - mn);
            m_i[i] = mn;
            l_i[i] *= cor;
#pragma unroll
            for (int jj = 0; jj < 8; jj++) acc[i][jj] *= cor;
            float ps = 0.f;
#pragma unroll
            for (int j = 0; j < 4; j++) {
                float p = __expf(s_acc[i][j] - mn);
                sP[(tx * 4 + j) * 68 + (ty * 4 + i)] = p;
                ps += p;
            }
            psum[i] = ps;
        }
#pragma unroll
        for (int off = 8; off > 0; off >>= 1)
#pragma unroll
            for (int i = 0; i < 4; i++)
                psum[i] += __shfl_xor_sync(0xffffffffu, psum[i], off);
#pragma unroll
        for (int i = 0; i < 4; i++) l_i[i] += psum[i];

        {
            const int d4 = tid & 31;
            const int c0 = tid >> 5;
#pragma unroll
            for (int i = 0; i < 8; i++) {
                int c = c0 + i * 8;
                float4 v4 = *(const float4*)(V + ((size_t)(b * Sn + jt * 64 + c) * Dn
                                                  + h * DHn + d4 * 4));
                *(float4*)&sKV[c * 128 + d4 * 4] = v4;
            }
        }
        __syncthreads();

#pragma unroll 4
        for (int c = 0; c < 64; c++) {
            float4 pa = *(const float4*)&sP[c * 68 + ty * 4];
            float4 v0 = *(const float4*)&sKV[c * 128 + tx * 8];
            float4 v1 = *(const float4*)&sKV[c * 128 + tx * 8 + 4];
            float pr[4] = {pa.x, pa.y, pa.z, pa.w};
            float vr[8] = {v0.x, v0.y, v0.z, v0.w, v1.x, v1.y, v1.z, v1.w};
#pragma unroll
            for (int i = 0; i < 4; i++)
#pragma unroll
                for (int jj = 0; jj < 8; jj++)
                    acc[i][jj] = fmaf(pr[i], vr[jj], acc[i][jj]);
        }
        __syncthreads();
    }

#pragma unroll
    for (int i = 0; i < 4; i++) {
        float inv_l = 1.f / l_i[i];
        size_t row = (size_t)(b * Sn + qt * 64 + ty * 4 + i) * Dn + h * DHn + tx * 8;
        float4 o0 = make_float4(acc[i][0] * inv_l, acc[i][1] * inv_l,
                                acc[i][2] * inv_l, acc[i][3] * inv_l);
        float4 o1 = make_float4(acc[i][4] * inv_l, acc[i][5] * inv_l,
                                acc[i][6] * inv_l, acc[i][7] * inv_l);
        *(float4*)&O[row]     = o0;
        *(float4*)&O[row + 4] = o1;
    }
}

// ---------------------------------------------------------------------------
// Launch
// ---------------------------------------------------------------------------
extern "C" void kernel_launch(void* const* d_in, const int* in_sizes, int n_in,
                              void* d_out, int out_size)
{
    const float* x     = (const float*)d_in[0];
    const float* q_w   = (const float*)d_in[1];
    const float* k_w   = (const float*)d_in[2];
    const float* v_w   = (const float*)d_in[3];
    const float* q_b   = (const float*)d_in[4];
    const float* k_b   = (const float*)d_in[5];
    const float* v_b   = (const float*)d_in[6];
    const float* out_w = (const float*)d_in[7];
    const float* out_b = (const float*)d_in[8];
    float* out = (float*)d_out;

    float *pQ, *pK, *pV, *pO;
    cudaGetSymbolAddress((void**)&pQ, g_Q);
    cudaGetSymbolAddress((void**)&pK, g_K);
    cudaGetSymbolAddress((void**)&pV, g_V);
    cudaGetSymbolAddress((void**)&pO, g_O);

    __nv_bfloat16 *xh, *xl, *Oh, *Ol, *qwh, *qwl, *kwh, *kwl, *vwh, *vwl, *owh, *owl;
    cudaGetSymbolAddress((void**)&xh,  g_xh);  cudaGetSymbolAddress((void**)&xl,  g_xl);
    cudaGetSymbolAddress((void**)&Oh,  g_Oh);  cudaGetSymbolAddress((void**)&Ol,  g_Ol);
    cudaGetSymbolAddress((void**)&qwh, g_qwh); cudaGetSymbolAddress((void**)&qwl, g_qwl);
    cudaGetSymbolAddress((void**)&kwh, g_kwh); cudaGetSymbolAddress((void**)&kwl, g_kwl);
    cudaGetSymbolAddress((void**)&vwh, g_vwh); cudaGetSymbolAddress((void**)&vwl, g_vwl);
    cudaGetSymbolAddress((void**)&owh, g_owh); cudaGetSymbolAddress((void**)&owl, g_owl);

    cudaFuncSetAttribute(flash_attn_kernel,
                         cudaFuncAttributeMaxDynamicSharedMemorySize, FA_SMEM_BYTES);
    cudaFuncSetAttribute(gemm_mma,
                         cudaFuncAttributeMaxDynamicSharedMemorySize, GEMM_SMEM);

    const int nx4 = Mn * Dn / 4;   // float4 count
    const int nw4 = Dn * Dn / 4;

    split_bf16_kernel<<<(nx4 + 255) / 256, 256>>>(x,     xh,  xl,  nx4);
    split_bf16_kernel<<<(nw4 + 255) / 256, 256>>>(q_w,   qwh, qwl, nw4);
    split_bf16_kernel<<<(nw4 + 255) / 256, 256>>>(k_w,   kwh, kwl, nw4);
    split_bf16_kernel<<<(nw4 + 255) / 256, 256>>>(v_w,   vwh, vwl, nw4);
    split_bf16_kernel<<<(nw4 + 255) / 256, 256>>>(out_w, owh, owl, nw4);

    dim3 gg(Dn / 128, Mn / 128);   // (16, 32)
    gemm_mma<<<gg, 256, GEMM_SMEM>>>(xh, xl, qwh, qwl, q_b, pQ);
    gemm_mma<<<gg, 256, GEMM_SMEM>>>(xh, xl, kwh, kwl, k_b, pK);
    gemm_mma<<<gg, 256, GEMM_SMEM>>>(xh, xl, vwh, vwl, v_b, pV);

    rope_table_kernel<<<(Sn * 64 + 255) / 256, 256>>>();
    rope_apply_kernel<<<(Bn * Sn * Hn * 64 + 255) / 256, 256>>>(pQ);
    rope_apply_kernel<<<(Bn * Sn * Hn * 64 + 255) / 256, 256>>>(pK);

    flash_attn_kernel<<<dim3(Sn / 64, Bn * Hn), 256, FA_SMEM_BYTES>>>(pQ, pK, pV, pO);

    split_bf16_kernel<<<(nx4 + 255) / 256, 256>>>(pO, Oh, Ol, nx4);
    gemm_mma<<<gg, 256, GEMM_SMEM>>>(Oh, Ol, owh, owl, out_b, out);
}

// round 7
// speedup vs baseline: 2.8844x; 1.9697x over previous
#include <cuda_runtime.h>
#include <cuda_bf16.h>
#include <cstdint>
#include <math.h>

// Problem constants
#define Bn  2
#define Sn  2048
#define Dn  2048
#define Hn  16
#define DHn 128
#define Mn  (Bn*Sn)          // 4096 rows for all GEMMs

// ---------------------------------------------------------------------------
// Scratch (no allocation allowed -> __device__ globals)
// ---------------------------------------------------------------------------
__device__ float g_Q[(size_t)Mn*Dn];
__device__ float g_K[(size_t)Mn*Dn];
__device__ float g_V[(size_t)Mn*Dn];
__device__ float g_O[(size_t)Mn*Dn];
__device__ float g_ct[Sn*64];
__device__ float g_st[Sn*64];

// bf16 split copies
__device__ __nv_bfloat16 g_xh[(size_t)Mn*Dn],  g_xl[(size_t)Mn*Dn];
__device__ __nv_bfloat16 g_Oh[(size_t)Mn*Dn],  g_Ol[(size_t)Mn*Dn];   // V splits, then O splits
__device__ __nv_bfloat16 g_Qh[(size_t)Mn*Dn],  g_Ql[(size_t)Mn*Dn];
__device__ __nv_bfloat16 g_Kh[(size_t)Mn*Dn],  g_Kl[(size_t)Mn*Dn];
__device__ __nv_bfloat16 g_qwh[(size_t)Dn*Dn], g_qwl[(size_t)Dn*Dn];
__device__ __nv_bfloat16 g_kwh[(size_t)Dn*Dn], g_kwl[(size_t)Dn*Dn];
__device__ __nv_bfloat16 g_vwh[(size_t)Dn*Dn], g_vwl[(size_t)Dn*Dn];
__device__ __nv_bfloat16 g_owh[(size_t)Dn*Dn], g_owl[(size_t)Dn*Dn];

__device__ __forceinline__ uint32_t smem_u32(const void* p) {
    uint32_t a;
    asm("{ .reg .u64 t; cvta.to.shared.u64 t, %1; cvt.u32.u64 %0, t; }"
        : "=r"(a) : "l"(p));
    return a;
}

#define CP_ASYNC16(smem_addr, gptr) \
    asm volatile("cp.async.cg.shared.global [%0], [%1], 16;" \
                 :: "r"(smem_addr), "l"(gptr) : "memory")
#define CP_COMMIT()  asm volatile("cp.async.commit_group;" ::: "memory")
#define CP_WAIT2()   asm volatile("cp.async.wait_group 2;"  ::: "memory")
#define CP_WAIT0()   asm volatile("cp.async.wait_group 0;"  ::: "memory")

#define LDSM_X4(r0,r1,r2,r3, addr) \
    asm volatile("ldmatrix.sync.aligned.m8n8.x4.shared.b16 {%0,%1,%2,%3}, [%4];" \
        : "=r"(r0),"=r"(r1),"=r"(r2),"=r"(r3) : "r"(addr))
#define LDSM_X4T(r0,r1,r2,r3, addr) \
    asm volatile("ldmatrix.sync.aligned.m8n8.x4.trans.shared.b16 {%0,%1,%2,%3}, [%4];" \
        : "=r"(r0),"=r"(r1),"=r"(r2),"=r"(r3) : "r"(addr))
#define MMA16816(d, a0,a1,a2,a3, b0,b1) \
    asm volatile("mma.sync.aligned.m16n8k16.row.col.f32.bf16.bf16.f32 " \
        "{%0,%1,%2,%3}, {%4,%5,%6,%7}, {%8,%9}, {%0,%1,%2,%3};" \
        : "+f"((d)[0]),"+f"((d)[1]),"+f"((d)[2]),"+f"((d)[3]) \
        : "r"(a0),"r"(a1),"r"(a2),"r"(a3), "r"(b0),"r"(b1))

__device__ __forceinline__ uint32_t pack_bf16(float lo, float hi) {
    __nv_bfloat162 t;
    t.x = __float2bfloat16(lo);
    t.y = __float2bfloat16(hi);
    return *(uint32_t*)&t;
}

// ---------------------------------------------------------------------------
// bf16 split conversion: hi = bf16(v), lo = bf16(v - hi)
// ---------------------------------------------------------------------------
__global__ void split_bf16_kernel(const float* __restrict__ src,
                                  __nv_bfloat16* __restrict__ hi,
                                  __nv_bfloat16* __restrict__ lo, int n4)
{
    int i = blockIdx.x * blockDim.x + threadIdx.x;
    if (i >= n4) return;
    float4 v = ((const float4*)src)[i];
    __nv_bfloat16 h0 = __float2bfloat16(v.x);
    __nv_bfloat16 h1 = __float2bfloat16(v.y);
    __nv_bfloat16 h2 = __float2bfloat16(v.z);
    __nv_bfloat16 h3 = __float2bfloat16(v.w);
    __nv_bfloat162 hh0, hh1, ll0, ll1;
    hh0.x = h0; hh0.y = h1; hh1.x = h2; hh1.y = h3;
    ll0.x = __float2bfloat16(v.x - __bfloat162float(h0));
    ll0.y = __float2bfloat16(v.y - __bfloat162float(h1));
    ll1.x = __float2bfloat16(v.z - __bfloat162float(h2));
    ll1.y = __float2bfloat16(v.w - __bfloat162float(h3));
    ((__nv_bfloat162*)hi)[i*2]   = hh0;
    ((__nv_bfloat162*)hi)[i*2+1] = hh1;
    ((__nv_bfloat162*)lo)[i*2]   = ll0;
    ((__nv_bfloat162*)lo)[i*2+1] = ll1;
}

// ---------------------------------------------------------------------------
// Split-bf16 GEMM (cp.async 4-stage pipeline), unchanged from R4.
// ---------------------------------------------------------------------------
#define GK       2048
#define NCHUNK   192
#define TILE_BYTES  10240
#define STAGE_BYTES (2*TILE_BYTES)
#define STAGES   4
#define GEMM_SMEM (STAGES*STAGE_BYTES)

__global__ __launch_bounds__(256, 2) void gemm_mma(
    const __nv_bfloat16* __restrict__ Ah, const __nv_bfloat16* __restrict__ Al,
    const __nv_bfloat16* __restrict__ Wh, const __nv_bfloat16* __restrict__ Wl,
    const float* __restrict__ bias, float* __restrict__ C)
{
    extern __shared__ __align__(16) char smem[];

    const int tid = threadIdx.x;
    const int lid = tid & 31;
    const int wid = tid >> 5;
    const int wm  = wid & 1;
    const int wn  = wid >> 1;
    const int bn  = blockIdx.x * 128;
    const int bm  = blockIdx.y * 128;
    const uint32_t sb = smem_u32(smem);

    const int gr = tid >> 2;
    const int gc = (tid & 3) * 8;

    const uint32_t sA0 = sb + (uint32_t)(gr * 80 + gc * 2);
    const uint32_t sA1 = sA0 + 64 * 80;
    const uint32_t sB0 = sA0 + TILE_BYTES;
    const uint32_t sB1 = sA1 + TILE_BYTES;

    float acc[4][4][4];
#pragma unroll
    for (int a = 0; a < 4; a++)
#pragma unroll
        for (int b = 0; b < 4; b++)
#pragma unroll
            for (int c = 0; c < 4; c++) acc[a][b][c] = 0.f;

    auto issue = [&](int ci) {
        int seg = ci >> 6;
        int k0  = (ci & 63) << 5;
        const __nv_bfloat16* As = (seg == 1) ? Al : Ah;
        const __nv_bfloat16* Ws = (seg == 2) ? Wl : Wh;
        uint32_t off = (uint32_t)(ci & (STAGES - 1)) * STAGE_BYTES;
        CP_ASYNC16(sA0 + off, As + (size_t)(bm + gr)      * GK + k0 + gc);
        CP_ASYNC16(sA1 + off, As + (size_t)(bm + gr + 64) * GK + k0 + gc);
        CP_ASYNC16(sB0 + off, Ws + (size_t)(bn + gr)      * GK + k0 + gc);
        CP_ASYNC16(sB1 + off, Ws + (size_t)(bn + gr + 64) * GK + k0 + gc);
        CP_COMMIT();
    };

    const uint32_t a_base = sb + (uint32_t)(wm * 64 + (lid & 15)) * 80
                          + ((lid >> 4) << 4);
    const uint32_t b_base = sb + TILE_BYTES
                          + (uint32_t)(wn * 32 + ((lid >> 4) << 3) + (lid & 7)) * 80
                          + (((lid >> 3) & 1) << 4);

    issue(0); issue(1); issue(2);

    for (int i = 0; i < NCHUNK; i++) {
        CP_WAIT2();
        __syncthreads();
        if (i + 3 < NCHUNK) issue(i + 3);

        const uint32_t off  = (uint32_t)(i & (STAGES - 1)) * STAGE_BYTES;
        const uint32_t abuf = a_base + off;
        const uint32_t bbuf = b_base + off;
#pragma unroll
        for (int k16 = 0; k16 < 2; k16++) {
            uint32_t af[4][4], bf[4][2];
#pragma unroll
            for (int mi = 0; mi < 4; mi++) {
                uint32_t ad = abuf + mi * (16 * 80) + k16 * 32;
                LDSM_X4(af[mi][0], af[mi][1], af[mi][2], af[mi][3], ad);
            }
#pragma unroll
            for (int nj = 0; nj < 2; nj++) {
                uint32_t bd = bbuf + nj * (16 * 80) + k16 * 32;
                LDSM_X4(bf[2*nj][0], bf[2*nj][1], bf[2*nj+1][0], bf[2*nj+1][1], bd);
            }
#pragma unroll
            for (int mi = 0; mi < 4; mi++)
#pragma unroll
                for (int ni = 0; ni < 4; ni++)
                    MMA16816(acc[mi][ni], af[mi][0], af[mi][1], af[mi][2], af[mi][3],
                             bf[ni][0], bf[ni][1]);
        }
    }

    const int g   = lid >> 2;
    const int tg2 = (lid & 3) * 2;
#pragma unroll
    for (int ni = 0; ni < 4; ni++) {
        const int col = bn + wn * 32 + ni * 8 + tg2;
        const float b0 = bias[col], b1 = bias[col + 1];
#pragma unroll
        for (int mi = 0; mi < 4; mi++) {
            const int row = bm + wm * 64 + mi * 16 + g;
            float2 v0 = make_float2(acc[mi][ni][0] + b0, acc[mi][ni][1] + b1);
            float2 v1 = make_float2(acc[mi][ni][2] + b0, acc[mi][ni][3] + b1);
            *(float2*)(C + (size_t)row * Dn + col)       = v0;
            *(float2*)(C + (size_t)(row + 8) * Dn + col) = v1;
        }
    }
}

// ---------------------------------------------------------------------------
// RoPE cos/sin table in fp64 (exact angles)
// ---------------------------------------------------------------------------
__global__ void rope_table_kernel()
{
    int idx = blockIdx.x * blockDim.x + threadIdx.x;
    if (idx >= Sn * 64) return;
    int i = idx & 63;
    int s = idx >> 6;
    double inv = exp((double)(-2 * i) * (9.210340371976182736 / 128.0)); // ln(1e4)
    double ang = (double)s * inv;
    g_ct[idx] = (float)cos(ang);
    g_st[idx] = (float)sin(ang);
}

// ---------------------------------------------------------------------------
// Fused RoPE apply + bf16 split (+ optional scale). Reads fp32, writes hi/lo bf16.
// ---------------------------------------------------------------------------
__global__ void rope_split_kernel(const float* __restrict__ X,
                                  __nv_bfloat16* __restrict__ Xh,
                                  __nv_bfloat16* __restrict__ Xl, float scale)
{
    int idx = blockIdx.x * blockDim.x + threadIdx.x;
    if (idx >= Bn * Sn * Hn * 64) return;
    int i = idx & 63;
    int h = (idx >> 6) & (Hn - 1);
    int s = (idx >> 10) & (Sn - 1);
    int b = idx >> 21;
    size_t base = (size_t)(b * Sn + s) * Dn + h * DHn;
    float c  = g_ct[(s << 6) | i];
    float sv = g_st[(s << 6) | i];
    float x1 = X[base + i];
    float x2 = X[base + 64 + i];
    float y1 = (x1 * c - x2 * sv) * scale;
    float y2 = (x2 * c + x1 * sv) * scale;
    __nv_bfloat16 h1 = __float2bfloat16(y1);
    __nv_bfloat16 h2 = __float2bfloat16(y2);
    Xh[base + i]      = h1;
    Xh[base + 64 + i] = h2;
    Xl[base + i]      = __float2bfloat16(y1 - __bfloat162float(h1));
    Xl[base + 64 + i] = __float2bfloat16(y2 - __bfloat162float(h2));
}

// ---------------------------------------------------------------------------
// Flash attention on tensor cores, split-bf16 3-term for both S and PV.
// Br=128, Bc=64, 8 warps (m16 per warp). P stays in registers.
// smem: Qh,Ql [128][128bf16 rows padded to 272B]; double-buffered K/V tiles.
// ---------------------------------------------------------------------------
#define QROW    272
#define SQL_OFF 34816            // 128*272
#define SKV_OFF 69632
#define KL_OFF  17408            // 64*272
#define VH_OFF  34816
#define VL_OFF  52224
#define FAB_SZ  69632            // Kh+Kl+Vh+Vl per buffer
#define FAM_SMEM (SKV_OFF + 2*FAB_SZ)   // 208896

__global__ __launch_bounds__(256, 1) void flash_attn_mma(
    const __nv_bfloat16* __restrict__ Qh, const __nv_bfloat16* __restrict__ Ql,
    const __nv_bfloat16* __restrict__ Kh, const __nv_bfloat16* __restrict__ Kl,
    const __nv_bfloat16* __restrict__ Vh, const __nv_bfloat16* __restrict__ Vl,
    float* __restrict__ O)
{
    extern __shared__ __align__(16) char sm[];
    const uint32_t sb = smem_u32(sm);
    const int tid = threadIdx.x, lid = tid & 31, wid = tid >> 5;
    const int qt = blockIdx.x;          // 0..15
    const int bh = blockIdx.y;          // 0..31
    const int b = bh >> 4, h = bh & 15;

    // ---- Q tile load (part of cp.async group 0) ----
    {
        const size_t qrow0 = (size_t)(b * Sn + qt * 128);
#pragma unroll
        for (int p = 0; p < 8; p++) {
            int idx = tid + p * 256;           // 0..2047
            int r = idx >> 4, c = idx & 15;
            size_t g = (qrow0 + r) * Dn + h * DHn + c * 8;
            uint32_t so = (uint32_t)(r * QROW + c * 16);
            CP_ASYNC16(sb + so,           Qh + g);
            CP_ASYNC16(sb + SQL_OFF + so, Ql + g);
        }
    }

    auto issue = [&](int j) {
        const uint32_t kb = sb + SKV_OFF + (uint32_t)(j & 1) * FAB_SZ;
        const size_t krow0 = (size_t)(b * Sn + j * 64);
#pragma unroll
        for (int p = 0; p < 4; p++) {
            int idx = tid + p * 256;           // 0..1023
            int r = idx >> 4, c = idx & 15;
            size_t g = (krow0 + r) * Dn + h * DHn + c * 8;
            uint32_t so = (uint32_t)(r * QROW + c * 16);
            CP_ASYNC16(kb + so,          Kh + g);
            CP_ASYNC16(kb + KL_OFF + so, Kl + g);
            CP_ASYNC16(kb + VH_OFF + so, Vh + g);
            CP_ASYNC16(kb + VL_OFF + so, Vl + g);
        }
        CP_COMMIT();
    };
    issue(0);

    // per-lane ldmatrix offsets
    const uint32_t aoff = (uint32_t)((wid * 16 + (lid & 15)) * QROW + ((lid >> 4) << 4));
    const uint32_t boff = (uint32_t)(((((lid >> 4) << 3) + (lid & 7))) * QROW
                                     + (((lid >> 3) & 1) << 4));
    const uint32_t voff = (uint32_t)((((lid & 7) + (((lid >> 3) & 1) << 3))) * QROW
                                     + ((lid >> 4) << 4));

    float oacc[16][4];
#pragma unroll
    for (int i = 0; i < 16; i++)
#pragma unroll
        for (int j = 0; j < 4; j++) oacc[i][j] = 0.f;
    float m0 = -1e30f, m1 = -1e30f, l0 = 0.f, l1 = 0.f;

    for (int j = 0; j < Sn / 64; j++) {
        CP_WAIT0();
        __syncthreads();
        if (j + 1 < Sn / 64) issue(j + 1);
        const uint32_t kb = sb + SKV_OFF + (uint32_t)(j & 1) * FAB_SZ;

        // ---- S = Q K^T (3 passes fused per k-step) ----
        float sacc[8][4];
#pragma unroll
        for (int t = 0; t < 8; t++)
#pragma unroll
            for (int c = 0; c < 4; c++) sacc[t][c] = 0.f;

#pragma unroll
        for (int t = 0; t < 8; t++) {
            uint32_t ah[4], al[4];
            LDSM_X4(ah[0], ah[1], ah[2], ah[3], sb + aoff + t * 32);
            LDSM_X4(al[0], al[1], al[2], al[3], sb + SQL_OFF + aoff + t * 32);
#pragma unroll
            for (int nj = 0; nj < 4; nj++) {
                uint32_t bh4[4], bl4[4];
                uint32_t bad = kb + boff + nj * (16 * QROW) + t * 32;
                LDSM_X4(bh4[0], bh4[1], bh4[2], bh4[3], bad);
                MMA16816(sacc[2*nj],   ah[0], ah[1], ah[2], ah[3], bh4[0], bh4[1]);
                MMA16816(sacc[2*nj+1], ah[0], ah[1], ah[2], ah[3], bh4[2], bh4[3]);
                MMA16816(sacc[2*nj],   al[0], al[1], al[2], al[3], bh4[0], bh4[1]);
                MMA16816(sacc[2*nj+1], al[0], al[1], al[2], al[3], bh4[2], bh4[3]);
                LDSM_X4(bl4[0], bl4[1], bl4[2], bl4[3], bad + KL_OFF);
                MMA16816(sacc[2*nj],   ah[0], ah[1], ah[2], ah[3], bl4[0], bl4[1]);
                MMA16816(sacc[2*nj+1], ah[0], ah[1], ah[2], ah[3], bl4[2], bl4[3]);
            }
        }

        // ---- online softmax (rows g and g+8 per lane) ----
        float mx0 = sacc[0][0], mx1 = sacc[0][2];
#pragma unroll
        for (int t = 0; t < 8; t++) {
            mx0 = fmaxf(mx0, fmaxf(sacc[t][0], sacc[t][1]));
            mx1 = fmaxf(mx1, fmaxf(sacc[t][2], sacc[t][3]));
        }
        mx0 = fmaxf(mx0, __shfl_xor_sync(0xffffffffu, mx0, 1));
        mx0 = fmaxf(mx0, __shfl_xor_sync(0xffffffffu, mx0, 2));
        mx1 = fmaxf(mx1, __shfl_xor_sync(0xffffffffu, mx1, 1));
        mx1 = fmaxf(mx1, __shfl_xor_sync(0xffffffffu, mx1, 2));

        const float mn0 = fmaxf(m0, mx0);
        const float mn1 = fmaxf(m1, mx1);
        const float cor0 = __expf(m0 - mn0);
        const float cor1 = __expf(m1 - mn1);
        m0 = mn0; m1 = mn1;
#pragma unroll
        for (int nt = 0; nt < 16; nt++) {
            oacc[nt][0] *= cor0; oacc[nt][1] *= cor0;
            oacc[nt][2] *= cor1; oacc[nt][3] *= cor1;
        }

        uint32_t pf[4][4], pl[4][4];
        float s0 = 0.f, s1 = 0.f;
#pragma unroll
        for (int jt = 0; jt < 8; jt++) {
            float p0 = __expf(sacc[jt][0] - mn0);
            float p1 = __expf(sacc[jt][1] - mn0);
            float p2 = __expf(sacc[jt][2] - mn1);
            float p3 = __expf(sacc[jt][3] - mn1);
            s0 += p0 + p1; s1 += p2 + p3;
            __nv_bfloat16 q0 = __float2bfloat16(p0);
            __nv_bfloat16 q1 = __float2bfloat16(p1);
            __nv_bfloat16 q2 = __float2bfloat16(p2);
            __nv_bfloat16 q3 = __float2bfloat16(p3);
            __nv_bfloat162 hA, hB, lA, lB;
            hA.x = q0; hA.y = q1;
            hB.x = q2; hB.y = q3;
            lA.x = __float2bfloat16(p0 - __bfloat162float(q0));
            lA.y = __float2bfloat16(p1 - __bfloat162float(q1));
            lB.x = __float2bfloat16(p2 - __bfloat162float(q2));
            lB.y = __float2bfloat16(p3 - __bfloat162float(q3));
            const int t = jt >> 1, o = (jt & 1) * 2;
            pf[t][o]     = *(uint32_t*)&hA;
            pf[t][o + 1] = *(uint32_t*)&hB;
            pl[t][o]     = *(uint32_t*)&lA;
            pl[t][o + 1] = *(uint32_t*)&lB;
        }
        s0 += __shfl_xor_sync(0xffffffffu, s0, 1);
        s0 += __shfl_xor_sync(0xffffffffu, s0, 2);
        s1 += __shfl_xor_sync(0xffffffffu, s1, 1);
        s1 += __shfl_xor_sync(0xffffffffu, s1, 2);
        l0 = l0 * cor0 + s0;
        l1 = l1 * cor1 + s1;

        // ---- O += P V (3 passes) ----
#pragma unroll
        for (int t = 0; t < 4; t++) {
#pragma unroll
            for (int p = 0; p < 8; p++) {
                uint32_t vh4[4], vl4[4];
                uint32_t vad = kb + VH_OFF + voff + t * (16 * QROW) + p * 32;
                LDSM_X4T(vh4[0], vh4[1], vh4[2], vh4[3], vad);
                MMA16816(oacc[2*p],   pf[t][0], pf[t][1], pf[t][2], pf[t][3], vh4[0], vh4[1]);
                MMA16816(oacc[2*p+1], pf[t][0], pf[t][1], pf[t][2], pf[t][3], vh4[2], vh4[3]);
                MMA16816(oacc[2*p],   pl[t][0], pl[t][1], pl[t][2], pl[t][3], vh4[0], vh4[1]);
                MMA16816(oacc[2*p+1], pl[t][0], pl[t][1], pl[t][2], pl[t][3], vh4[2], vh4[3]);
                LDSM_X4T(vl4[0], vl4[1], vl4[2], vl4[3], vad + KL_OFF);
                MMA16816(oacc[2*p],   pf[t][0], pf[t][1], pf[t][2], pf[t][3], vl4[0], vl4[1]);
                MMA16816(oacc[2*p+1], pf[t][0], pf[t][1], pf[t][2], pf[t][3], vl4[2], vl4[3]);
            }
        }
    }

    // ---- normalize + write ----
    const float i0 = 1.f / l0, i1 = 1.f / l1;
    const int g = lid >> 2, tg2 = (lid & 3) * 2;
    const size_t row = (size_t)(b * Sn + qt * 128 + wid * 16 + g);
#pragma unroll
    for (int nt = 0; nt < 16; nt++) {
        const int col = h * DHn + nt * 8 + tg2;
        float2 v0 = make_float2(oacc[nt][0] * i0, oacc[nt][1] * i0);
        float2 v1 = make_float2(oacc[nt][2] * i1, oacc[nt][3] * i1);
        *(float2*)(O + row * Dn + col)       = v0;
        *(float2*)(O + (row + 8) * Dn + col) = v1;
    }
}

// ---------------------------------------------------------------------------
// Launch
// ---------------------------------------------------------------------------
extern "C" void kernel_launch(void* const* d_in, const int* in_sizes, int n_in,
                              void* d_out, int out_size)
{
    const float* x     = (const float*)d_in[0];
    const float* q_w   = (const float*)d_in[1];
    const float* k_w   = (const float*)d_in[2];
    const float* v_w   = (const float*)d_in[3];
    const float* q_b   = (const float*)d_in[4];
    const float* k_b   = (const float*)d_in[5];
    const float* v_b   = (const float*)d_in[6];
    const float* out_w = (const float*)d_in[7];
    const float* out_b = (const float*)d_in[8];
    float* out = (float*)d_out;

    float *pQ, *pK, *pV, *pO;
    cudaGetSymbolAddress((void**)&pQ, g_Q);
    cudaGetSymbolAddress((void**)&pK, g_K);
    cudaGetSymbolAddress((void**)&pV, g_V);
    cudaGetSymbolAddress((void**)&pO, g_O);

    __nv_bfloat16 *xh, *xl, *Oh, *Ol, *Qh, *Ql, *Kh, *Kl;
    __nv_bfloat16 *qwh, *qwl, *kwh, *kwl, *vwh, *vwl, *owh, *owl;
    cudaGetSymbolAddress((void**)&xh,  g_xh);  cudaGetSymbolAddress((void**)&xl,  g_xl);
    cudaGetSymbolAddress((void**)&Oh,  g_Oh);  cudaGetSymbolAddress((void**)&Ol,  g_Ol);
    cudaGetSymbolAddress((void**)&Qh,  g_Qh);  cudaGetSymbolAddress((void**)&Ql,  g_Ql);
    cudaGetSymbolAddress((void**)&Kh,  g_Kh);  cudaGetSymbolAddress((void**)&Kl,  g_Kl);
    cudaGetSymbolAddress((void**)&qwh, g_qwh); cudaGetSymbolAddress((void**)&qwl, g_qwl);
    cudaGetSymbolAddress((void**)&kwh, g_kwh); cudaGetSymbolAddress((void**)&kwl, g_kwl);
    cudaGetSymbolAddress((void**)&vwh, g_vwh); cudaGetSymbolAddress((void**)&vwl, g_vwl);
    cudaGetSymbolAddress((void**)&owh, g_owh); cudaGetSymbolAddress((void**)&owl, g_owl);

    cudaFuncSetAttribute(gemm_mma,
                         cudaFuncAttributeMaxDynamicSharedMemorySize, GEMM_SMEM);
    cudaFuncSetAttribute(flash_attn_mma,
                         cudaFuncAttributeMaxDynamicSharedMemorySize, FAM_SMEM);

    const int nx4 = Mn * Dn / 4;
    const int nw4 = Dn * Dn / 4;

    split_bf16_kernel<<<(nx4 + 255) / 256, 256>>>(x,     xh,  xl,  nx4);
    split_bf16_kernel<<<(nw4 + 255) / 256, 256>>>(q_w,   qwh, qwl, nw4);
    split_bf16_kernel<<<(nw4 + 255) / 256, 256>>>(k_w,   kwh, kwl, nw4);
    split_bf16_kernel<<<(nw4 + 255) / 256, 256>>>(v_w,   vwh, vwl, nw4);
    split_bf16_kernel<<<(nw4 + 255) / 256, 256>>>(out_w, owh, owl, nw4);

    dim3 gg(Dn / 128, Mn / 128);   // (16, 32)
    gemm_mma<<<gg, 256, GEMM_SMEM>>>(xh, xl, qwh, qwl, q_b, pQ);
    gemm_mma<<<gg, 256, GEMM_SMEM>>>(xh, xl, kwh, kwl, k_b, pK);
    gemm_mma<<<gg, 256, GEMM_SMEM>>>(xh, xl, vwh, vwl, v_b, pV);

    rope_table_kernel<<<(Sn * 64 + 255) / 256, 256>>>();
    const int nr = Bn * Sn * Hn * 64;
    rope_split_kernel<<<(nr + 255) / 256, 256>>>(pQ, Qh, Ql, 0.088388347648318447f);
    rope_split_kernel<<<(nr + 255) / 256, 256>>>(pK, Kh, Kl, 1.0f);
    split_bf16_kernel<<<(nx4 + 255) / 256, 256>>>(pV, Oh, Ol, nx4);  // V splits

    flash_attn_mma<<<dim3(Sn / 128, Bn * Hn), 256, FAM_SMEM>>>(
        Qh, Ql, Kh, Kl, Oh, Ol, pO);

    split_bf16_kernel<<<(nx4 + 255) / 256, 256>>>(pO, Oh, Ol, nx4);  // O splits
    gemm_mma<<<gg, 256, GEMM_SMEM>>>(Oh, Ol, owh, owl, out_b, out);
}